// round 2
// baseline (speedup 1.0000x reference)
#include <cuda_runtime.h>
#include <math.h>

#define NCOMP 36
#define GRID_R 300
#define HID 256
#define INCH 129
#define OUTCH 129
#define TP 64

// Scratch: channel-last layouts for gather-friendly sampling.
__device__ float g_planesT[3 * GRID_R * GRID_R * NCOMP];  // [pl][y][x][c]
__device__ float g_linesT[3 * GRID_R * NCOMP];            // [pl][z][c]

// ---------------------------------------------------------------------------
// planes [3,36,300,300] -> planesT [3,300,300,36] via smem tile transpose
// ---------------------------------------------------------------------------
__global__ void k_transpose_planes(const float* __restrict__ planes) {
    __shared__ float tile[NCOMP * 64];
    int chunk = blockIdx.x % 5;
    int y     = (blockIdx.x / 5) % GRID_R;
    int pl    = blockIdx.x / (5 * GRID_R);
    int x0 = chunk * 64;
    int w  = min(64, GRID_R - x0);

    for (int idx = threadIdx.x; idx < NCOMP * w; idx += blockDim.x) {
        int c = idx / w;
        int x = idx - c * w;
        tile[c * 64 + x] = planes[((pl * NCOMP + c) * GRID_R + y) * GRID_R + x0 + x];
    }
    __syncthreads();
    float* outp = g_planesT + ((pl * GRID_R + y) * GRID_R + x0) * NCOMP;
    for (int idx = threadIdx.x; idx < w * NCOMP; idx += blockDim.x) {
        int x = idx / NCOMP;
        int c = idx - x * NCOMP;
        outp[idx] = tile[c * 64 + x];
    }
}

__global__ void k_transpose_lines(const float* __restrict__ lines) {
    int idx = blockIdx.x * blockDim.x + threadIdx.x;
    const int total = 3 * GRID_R * NCOMP;
    if (idx < total) {
        int c  = idx % NCOMP;
        int z  = (idx / NCOMP) % GRID_R;
        int pl = idx / (NCOMP * GRID_R);
        g_linesT[idx] = lines[(pl * NCOMP + c) * GRID_R + z];
    }
}

// ---------------------------------------------------------------------------
// Fused sample + embed + MLP kernel.
// 64 points per CTA, 256 threads.
// smem (floats):
//   Xs   [0,      8448)   mlp_in, layout [k(132 rows)][p(64)]
//   Ws   [8448,   16896)  phase-1 weight tile [jj(64)][k(132)]
//   W2s  [0,      16640)  phase-2 weight tile [oo(64)][k(260)]  (reuses Xs+Ws)
//   Hs   [16896,  33280)  hidden, layout [j(256)][p(64)]
//   Outs [33280,  37440)  output stage [oo(64)][p(65 stride)]
// ---------------------------------------------------------------------------
#define SMEM_FLOATS 37440
#define SMEM_BYTES  (SMEM_FLOATS * 4)

__global__ __launch_bounds__(256, 1) void k_main(
    const float* __restrict__ xyz,
    const float* __restrict__ w1, const float* __restrict__ b1,
    const float* __restrict__ w2, const float* __restrict__ b2,
    float* __restrict__ out, int npts)
{
    extern __shared__ float sm[];
    float* Xs   = sm;
    float* Ws   = sm + 132 * 64;
    float* W2s  = sm;
    float* Hs   = sm + 132 * 64 + 64 * 132;
    float* Outs = Hs + 256 * 64;

    const int tid = threadIdx.x;
    const int p = tid & 63;
    const int g = tid >> 6;          // 0..2: plane+line group, 3: embed
    const int P0 = blockIdx.x * TP;
    int P = P0 + p;
    if (P >= npts) P = npts - 1;

    const float x = xyz[P * 3 + 0];
    const float y = xyz[P * 3 + 1];
    const float z = xyz[P * 3 + 2];

    // ---------------- sampling / embedding ----------------
    if (g < 3) {
        // plane coords: g0:(x,y) line z; g1:(x,z) line y; g2:(y,z) line x
        float gx, gy, gl;
        if (g == 0)      { gx = x; gy = y; gl = z; }
        else if (g == 1) { gx = x; gy = z; gl = y; }
        else             { gx = y; gy = z; gl = x; }

        float fx = (gx + 1.f) * 0.5f * (float)(GRID_R - 1);
        float fy = (gy + 1.f) * 0.5f * (float)(GRID_R - 1);
        float fz = (gl + 1.f) * 0.5f * (float)(GRID_R - 1);
        int ix = min(max(__float2int_rd(fx), 0), GRID_R - 2);
        int iy = min(max(__float2int_rd(fy), 0), GRID_R - 2);
        int iz = min(max(__float2int_rd(fz), 0), GRID_R - 2);
        float tx = fx - (float)ix, ty = fy - (float)iy, tz = fz - (float)iz;

        float w00 = (1.f - tx) * (1.f - ty);
        float w01 = tx * (1.f - ty);
        float w10 = (1.f - tx) * ty;
        float w11 = tx * ty;
        float lz0 = 1.f - tz, lz1 = tz;

        const float* rowbase = g_planesT + ((g * GRID_R + iy) * GRID_R + ix) * NCOMP;
        const float4* b00 = (const float4*)(rowbase);
        const float4* b01 = (const float4*)(rowbase + NCOMP);
        const float4* b10 = (const float4*)(rowbase + GRID_R * NCOMP);
        const float4* b11 = (const float4*)(rowbase + GRID_R * NCOMP + NCOMP);
        const float4* l0p = (const float4*)(g_linesT + (g * GRID_R + iz) * NCOMP);
        const float4* l1p = (const float4*)(g_linesT + (g * GRID_R + iz + 1) * NCOMP);

        float* dst = Xs + (21 + g * NCOMP) * 64 + p;
        #pragma unroll
        for (int c4 = 0; c4 < 9; c4++) {
            float4 a  = b00[c4];
            float4 b  = b01[c4];
            float4 cc = b10[c4];
            float4 d  = b11[c4];
            float4 l0 = l0p[c4];
            float4 l1 = l1p[c4];
            dst[(c4 * 4 + 0) * 64] = (a.x * w00 + b.x * w01 + cc.x * w10 + d.x * w11) * (l0.x * lz0 + l1.x * lz1);
            dst[(c4 * 4 + 1) * 64] = (a.y * w00 + b.y * w01 + cc.y * w10 + d.y * w11) * (l0.y * lz0 + l1.y * lz1);
            dst[(c4 * 4 + 2) * 64] = (a.z * w00 + b.z * w01 + cc.z * w10 + d.z * w11) * (l0.z * lz0 + l1.z * lz1);
            dst[(c4 * 4 + 3) * 64] = (a.w * w00 + b.w * w01 + cc.w * w10 + d.w * w11) * (l0.w * lz0 + l1.w * lz1);
        }
    } else {
        // NeRF positional encoding, order: xyz | sin(i-major,f) | cos(i-major,f)
        Xs[0 * 64 + p] = x;
        Xs[1 * 64 + p] = y;
        Xs[2 * 64 + p] = z;
        const float v[3] = {x, y, z};
        #pragma unroll
        for (int i = 0; i < 3; i++) {
            #pragma unroll
            for (int f = 0; f < 3; f++) {
                float s, c;
                sincosf(v[i] * (float)(1 << f), &s, &c);
                Xs[(3  + i * 3 + f) * 64 + p] = s;
                Xs[(12 + i * 3 + f) * 64 + p] = c;
            }
        }
    }
    __syncthreads();

    const int tp = tid & 15;   // 16 tiles of 4 points
    const int tj = tid >> 4;   // 16 tiles of 4 j/o

    // ---------------- phase 1: h = softplus(100*(X @ w1^T + b1))/100 ----------------
    for (int pass = 0; pass < 4; pass++) {
        const int j0 = pass * 64;
        for (int idx = tid; idx < 64 * 132; idx += 256) {
            int jj = idx / 132;
            int k  = idx - jj * 132;
            Ws[idx] = (k < INCH) ? w1[(j0 + jj) * INCH + k] : 0.f;
        }
        __syncthreads();

        float acc[4][4];
        #pragma unroll
        for (int a = 0; a < 4; a++) {
            float bb = b1[j0 + 4 * tj + a];
            acc[a][0] = bb; acc[a][1] = bb; acc[a][2] = bb; acc[a][3] = bb;
        }
        const float* wr0 = Ws + (4 * tj + 0) * 132;
        const float* wr1 = Ws + (4 * tj + 1) * 132;
        const float* wr2 = Ws + (4 * tj + 2) * 132;
        const float* wr3 = Ws + (4 * tj + 3) * 132;

        #pragma unroll 3
        for (int k = 0; k < INCH; k++) {
            float4 xv = *(const float4*)(Xs + k * 64 + 4 * tp);
            float a0 = wr0[k], a1 = wr1[k], a2 = wr2[k], a3 = wr3[k];
            acc[0][0] += a0 * xv.x; acc[0][1] += a0 * xv.y; acc[0][2] += a0 * xv.z; acc[0][3] += a0 * xv.w;
            acc[1][0] += a1 * xv.x; acc[1][1] += a1 * xv.y; acc[1][2] += a1 * xv.z; acc[1][3] += a1 * xv.w;
            acc[2][0] += a2 * xv.x; acc[2][1] += a2 * xv.y; acc[2][2] += a2 * xv.z; acc[2][3] += a2 * xv.w;
            acc[3][0] += a3 * xv.x; acc[3][1] += a3 * xv.y; acc[3][2] += a3 * xv.z; acc[3][3] += a3 * xv.w;
        }

        #pragma unroll
        for (int a = 0; a < 4; a++) {
            #pragma unroll
            for (int b = 0; b < 4; b++) {
                float zz = 100.f * acc[a][b];
                float sp = fmaxf(zz, 0.f) + log1pf(expf(-fabsf(zz)));
                Hs[(j0 + 4 * tj + a) * 64 + 4 * tp + b] = sp * 0.01f;
            }
        }
        __syncthreads();
    }

    // ---------------- phase 2: out = H @ w2^T + b2 ----------------
    for (int pass = 0; pass < 3; pass++) {
        const int o0 = pass * 64;
        for (int idx = tid; idx < 64 * 260; idx += 256) {
            int oo = idx / 260;
            int k  = idx - oo * 260;
            int o  = o0 + oo;
            W2s[idx] = (o < OUTCH && k < HID) ? w2[o * HID + k] : 0.f;
        }
        __syncthreads();

        float acc[4][4];
        #pragma unroll
        for (int a = 0; a < 4; a++) {
            int o = o0 + 4 * tj + a;
            float bb = (o < OUTCH) ? b2[o] : 0.f;
            acc[a][0] = bb; acc[a][1] = bb; acc[a][2] = bb; acc[a][3] = bb;
        }
        const float* wr0 = W2s + (4 * tj + 0) * 260;
        const float* wr1 = W2s + (4 * tj + 1) * 260;
        const float* wr2 = W2s + (4 * tj + 2) * 260;
        const float* wr3 = W2s + (4 * tj + 3) * 260;

        #pragma unroll 4
        for (int k = 0; k < HID; k++) {
            float4 hv = *(const float4*)(Hs + k * 64 + 4 * tp);
            float a0 = wr0[k], a1 = wr1[k], a2 = wr2[k], a3 = wr3[k];
            acc[0][0] += a0 * hv.x; acc[0][1] += a0 * hv.y; acc[0][2] += a0 * hv.z; acc[0][3] += a0 * hv.w;
            acc[1][0] += a1 * hv.x; acc[1][1] += a1 * hv.y; acc[1][2] += a1 * hv.z; acc[1][3] += a1 * hv.w;
            acc[2][0] += a2 * hv.x; acc[2][1] += a2 * hv.y; acc[2][2] += a2 * hv.z; acc[2][3] += a2 * hv.w;
            acc[3][0] += a3 * hv.x; acc[3][1] += a3 * hv.y; acc[3][2] += a3 * hv.z; acc[3][3] += a3 * hv.w;
        }

        #pragma unroll
        for (int a = 0; a < 4; a++)
            #pragma unroll
            for (int b = 0; b < 4; b++)
                Outs[(4 * tj + a) * 65 + 4 * tp + b] = acc[a][b];
        __syncthreads();

        // coalesced store: 64 threads write 64 consecutive o for one point
        for (int r = 0; r < 64; r += 4) {
            int pp = r + (tid >> 6);
            int oo = tid & 63;
            int o  = o0 + oo;
            int Pg = P0 + pp;
            if (o < OUTCH && Pg < npts)
                out[Pg * OUTCH + o] = Outs[oo * 65 + pp];
        }
        __syncthreads();
    }
}

// ---------------------------------------------------------------------------
extern "C" void kernel_launch(void* const* d_in, const int* in_sizes, int n_in,
                              void* d_out, int out_size) {
    const float* xyz    = (const float*)d_in[0];
    const float* planes = (const float*)d_in[1];
    const float* lines  = (const float*)d_in[2];
    const float* w1     = (const float*)d_in[3];
    const float* b1     = (const float*)d_in[4];
    const float* w2     = (const float*)d_in[5];
    const float* b2     = (const float*)d_in[6];
    float* out = (float*)d_out;

    int npts = in_sizes[0] / 3;

    cudaFuncSetAttribute(k_main, cudaFuncAttributeMaxDynamicSharedMemorySize, SMEM_BYTES);

    k_transpose_planes<<<3 * GRID_R * 5, 256>>>(planes);
    k_transpose_lines<<<(3 * GRID_R * NCOMP + 255) / 256, 256>>>(lines);

    int blocks = (npts + TP - 1) / TP;
    k_main<<<blocks, 256, SMEM_BYTES>>>(xyz, w1, b1, w2, b2, out, npts);
}

// round 3
// speedup vs baseline: 1.7291x; 1.7291x over previous
#include <cuda_runtime.h>
#include <math.h>
#include <stdint.h>

#define NCOMP 36
#define GRID_R 300
#define HID 256
#define INCH 129
#define OUTCH 129
#define TP 64
#define SX 68    // Xs stride  (64 pts + 4 pad)
#define SW1 140  // W1s stride (136 + 4 pad)
#define SH 68    // Hs stride
#define SW2 260  // W2s stride (256 + 4 pad)
#define SO 68    // Outs stride

// smem float offsets
#define OFF_XS   0
#define OFF_W1S  (136 * SX)                 // 9248
#define OFF_HS   (OFF_W1S + 128 * SW1)      // 27168
#define OFF_OUTS (OFF_HS + 256 * SH)        // 44576
#define SMEM_FLOATS (OFF_OUTS + 72 * SO)    // 49472
#define SMEM_BYTES (SMEM_FLOATS * 4)
#define OFF_W2S  0                          // reuses Xs+W1s region in phase 2

// Scratch: channel-last layouts for gather-friendly sampling.
__device__ float g_planesT[3 * GRID_R * GRID_R * NCOMP];  // [pl][y][x][c]
__device__ float g_linesT[3 * GRID_R * NCOMP];            // [pl][z][c]

// ---------------------------------------------------------------------------
__global__ void k_transpose_planes(const float* __restrict__ planes) {
    __shared__ float tile[NCOMP * 64];
    int chunk = blockIdx.x % 5;
    int y     = (blockIdx.x / 5) % GRID_R;
    int pl    = blockIdx.x / (5 * GRID_R);
    int x0 = chunk * 64;
    int w  = min(64, GRID_R - x0);

    for (int idx = threadIdx.x; idx < NCOMP * w; idx += blockDim.x) {
        int c = idx / w;
        int x = idx - c * w;
        tile[c * 64 + x] = planes[((pl * NCOMP + c) * GRID_R + y) * GRID_R + x0 + x];
    }
    __syncthreads();
    float* outp = g_planesT + ((pl * GRID_R + y) * GRID_R + x0) * NCOMP;
    for (int idx = threadIdx.x; idx < w * NCOMP; idx += blockDim.x) {
        int x = idx / NCOMP;
        int c = idx - x * NCOMP;
        outp[idx] = tile[c * 64 + x];
    }
}

__global__ void k_transpose_lines(const float* __restrict__ lines) {
    int idx = blockIdx.x * blockDim.x + threadIdx.x;
    const int total = 3 * GRID_R * NCOMP;
    if (idx < total) {
        int c  = idx % NCOMP;
        int z  = (idx / NCOMP) % GRID_R;
        int pl = idx / (NCOMP * GRID_R);
        g_linesT[idx] = lines[(pl * NCOMP + c) * GRID_R + z];
    }
}

// ---------------------------------------------------------------------------
__device__ __forceinline__ uint32_t f2tf(float x) {
    uint32_t u;
    asm("cvt.rna.tf32.f32 %0, %1;" : "=r"(u) : "f"(x));
    return u;
}

__device__ __forceinline__ void mma_tf32(float* d, const uint32_t* a, const uint32_t* b) {
    asm volatile(
        "mma.sync.aligned.m16n8k8.row.col.f32.tf32.tf32.f32 "
        "{%0,%1,%2,%3}, {%4,%5,%6,%7}, {%8,%9}, {%0,%1,%2,%3};"
        : "+f"(d[0]), "+f"(d[1]), "+f"(d[2]), "+f"(d[3])
        : "r"(a[0]), "r"(a[1]), "r"(a[2]), "r"(a[3]), "r"(b[0]), "r"(b[1]));
}

// ---------------------------------------------------------------------------
// Fused sample + embed + tf32-tensor-core MLP.
// 64 points per CTA, 256 threads (8 warps: 2 M-warps x 4 N-warps).
// ---------------------------------------------------------------------------
__global__ __launch_bounds__(256, 1) void k_main(
    const float* __restrict__ xyz,
    const float* __restrict__ w1, const float* __restrict__ b1,
    const float* __restrict__ w2, const float* __restrict__ b2,
    float* __restrict__ out, int npts)
{
    extern __shared__ float sm[];
    uint32_t* smu = (uint32_t*)sm;
    float*    Xs   = sm  + OFF_XS;
    uint32_t* Xsu  = smu + OFF_XS;
    uint32_t* W1su = smu + OFF_W1S;
    float*    Hs   = sm  + OFF_HS;
    uint32_t* Hsu  = smu + OFF_HS;
    float*    Outs = sm  + OFF_OUTS;
    uint32_t* W2su = smu + OFF_W2S;

    const int tid = threadIdx.x;
    const int p = tid & 63;
    const int g = tid >> 6;  // 0..2: plane groups, 3: embed
    const int P0 = blockIdx.x * TP;
    int P = P0 + p;
    if (P >= npts) P = npts - 1;

    const float x = xyz[P * 3 + 0];
    const float y = xyz[P * 3 + 1];
    const float z = xyz[P * 3 + 2];

    // ---------------- sampling / embedding into Xs [k][p] (tf32 bits) -------
    if (g < 3) {
        float gx, gy, gl;
        if (g == 0)      { gx = x; gy = y; gl = z; }
        else if (g == 1) { gx = x; gy = z; gl = y; }
        else             { gx = y; gy = z; gl = x; }

        float fx = (gx + 1.f) * 0.5f * (float)(GRID_R - 1);
        float fy = (gy + 1.f) * 0.5f * (float)(GRID_R - 1);
        float fz = (gl + 1.f) * 0.5f * (float)(GRID_R - 1);
        int ix = min(max(__float2int_rd(fx), 0), GRID_R - 2);
        int iy = min(max(__float2int_rd(fy), 0), GRID_R - 2);
        int iz = min(max(__float2int_rd(fz), 0), GRID_R - 2);
        float tx = fx - (float)ix, ty = fy - (float)iy, tz = fz - (float)iz;

        float w00 = (1.f - tx) * (1.f - ty);
        float w01 = tx * (1.f - ty);
        float w10 = (1.f - tx) * ty;
        float w11 = tx * ty;
        float lz0 = 1.f - tz, lz1 = tz;

        const float* rowbase = g_planesT + ((g * GRID_R + iy) * GRID_R + ix) * NCOMP;
        const float4* b00 = (const float4*)(rowbase);
        const float4* b01 = (const float4*)(rowbase + NCOMP);
        const float4* b10 = (const float4*)(rowbase + GRID_R * NCOMP);
        const float4* b11 = (const float4*)(rowbase + GRID_R * NCOMP + NCOMP);
        const float4* l0p = (const float4*)(g_linesT + (g * GRID_R + iz) * NCOMP);
        const float4* l1p = (const float4*)(g_linesT + (g * GRID_R + iz + 1) * NCOMP);

        uint32_t* dst = Xsu + (21 + g * NCOMP) * SX + p;
        #pragma unroll
        for (int c4 = 0; c4 < 9; c4++) {
            float4 a  = b00[c4];
            float4 b  = b01[c4];
            float4 cc = b10[c4];
            float4 d  = b11[c4];
            float4 l0 = l0p[c4];
            float4 l1 = l1p[c4];
            dst[(c4 * 4 + 0) * SX] = f2tf((a.x * w00 + b.x * w01 + cc.x * w10 + d.x * w11) * (l0.x * lz0 + l1.x * lz1));
            dst[(c4 * 4 + 1) * SX] = f2tf((a.y * w00 + b.y * w01 + cc.y * w10 + d.y * w11) * (l0.y * lz0 + l1.y * lz1));
            dst[(c4 * 4 + 2) * SX] = f2tf((a.z * w00 + b.z * w01 + cc.z * w10 + d.z * w11) * (l0.z * lz0 + l1.z * lz1));
            dst[(c4 * 4 + 3) * SX] = f2tf((a.w * w00 + b.w * w01 + cc.w * w10 + d.w * w11) * (l0.w * lz0 + l1.w * lz1));
        }
    } else {
        Xsu[0 * SX + p] = f2tf(x);
        Xsu[1 * SX + p] = f2tf(y);
        Xsu[2 * SX + p] = f2tf(z);
        const float v[3] = {x, y, z};
        #pragma unroll
        for (int i = 0; i < 3; i++) {
            #pragma unroll
            for (int f = 0; f < 3; f++) {
                float s, c;
                sincosf(v[i] * (float)(1 << f), &s, &c);
                Xsu[(3  + i * 3 + f) * SX + p] = f2tf(s);
                Xsu[(12 + i * 3 + f) * SX + p] = f2tf(c);
            }
        }
    }
    // zero pad rows k = 129..135
    for (int i = tid; i < 7 * 64; i += 256)
        Xsu[(INCH + (i >> 6)) * SX + (i & 63)] = 0u;
    __syncthreads();

    const int warp  = tid >> 5;
    const int lane  = tid & 31;
    const int fg    = lane >> 2;  // 0..7
    const int fc    = lane & 3;   // 0..3
    const int warpM = warp >> 2;  // 0..1
    const int warpN = warp & 3;   // 0..3
    const int p0w   = warpM * 32;

    // ============ phase 1: H = softplus(100*(X @ w1^T + b1))/100 ============
    for (int pass = 0; pass < 2; pass++) {
        const int j0 = pass * 128;
        for (int idx = tid; idx < 128 * SW1; idx += 256) {
            int n = idx / SW1;
            int k = idx - n * SW1;
            float v = (k < INCH) ? w1[(j0 + n) * INCH + k] : 0.f;
            W1su[idx] = f2tf(v);
        }
        __syncthreads();

        float acc[2][4][4];
        #pragma unroll
        for (int nt = 0; nt < 4; nt++) {
            int j = j0 + warpN * 32 + nt * 8 + 2 * fc;
            float bb0 = b1[j], bb1 = b1[j + 1];
            #pragma unroll
            for (int mt = 0; mt < 2; mt++) {
                acc[mt][nt][0] = bb0; acc[mt][nt][1] = bb1;
                acc[mt][nt][2] = bb0; acc[mt][nt][3] = bb1;
            }
        }

        #pragma unroll
        for (int kt = 0; kt < 17; kt++) {
            const int k0 = kt * 8;
            uint32_t a[2][4];
            const int abase = (k0 + fc) * SX + p0w + fg;
            #pragma unroll
            for (int mt = 0; mt < 2; mt++) {
                a[mt][0] = Xsu[abase + mt * 16];
                a[mt][1] = Xsu[abase + mt * 16 + 8];
                a[mt][2] = Xsu[abase + mt * 16 + 4 * SX];
                a[mt][3] = Xsu[abase + mt * 16 + 8 + 4 * SX];
            }
            uint32_t b[4][2];
            #pragma unroll
            for (int nt = 0; nt < 4; nt++) {
                int baddr = (warpN * 32 + nt * 8 + fg) * SW1 + k0 + fc;
                b[nt][0] = W1su[baddr];
                b[nt][1] = W1su[baddr + 4];
            }
            #pragma unroll
            for (int mt = 0; mt < 2; mt++)
                #pragma unroll
                for (int nt = 0; nt < 4; nt++)
                    mma_tf32(acc[mt][nt], a[mt], b[nt]);
        }

        // softplus + store H (as tf32 bits)
        #pragma unroll
        for (int mt = 0; mt < 2; mt++) {
            #pragma unroll
            for (int nt = 0; nt < 4; nt++) {
                #pragma unroll
                for (int i = 0; i < 4; i++) {
                    int pp = p0w + mt * 16 + fg + ((i >> 1) ? 8 : 0);
                    int jj = j0 + warpN * 32 + nt * 8 + 2 * fc + (i & 1);
                    float zz = 100.f * acc[mt][nt][i];
                    float sp = (fmaxf(zz, 0.f) + log1pf(expf(-fabsf(zz)))) * 0.01f;
                    Hsu[jj * SH + pp] = f2tf(sp);
                }
            }
        }
        __syncthreads();
    }

    // ============ phase 2: out = H @ w2^T + b2 (2 passes x 72 outs) =========
    for (int po = 0; po < 2; po++) {
        const int o0 = po * 72;
        for (int idx = tid; idx < 72 * SW2; idx += 256) {
            int n = idx / SW2;
            int k = idx - n * SW2;
            int o = o0 + n;
            float v = (k < HID && o < OUTCH) ? w2[o * HID + k] : 0.f;
            W2su[idx] = f2tf(v);
        }
        __syncthreads();

        float acc[2][3][4];
        #pragma unroll
        for (int nti = 0; nti < 3; nti++) {
            int nt = warpN + nti * 4;
            if (nt >= 9) break;
            int o = o0 + nt * 8 + 2 * fc;
            float bb0 = (o < OUTCH) ? b2[o] : 0.f;
            float bb1 = (o + 1 < OUTCH) ? b2[o + 1] : 0.f;
            #pragma unroll
            for (int mt = 0; mt < 2; mt++) {
                acc[mt][nti][0] = bb0; acc[mt][nti][1] = bb1;
                acc[mt][nti][2] = bb0; acc[mt][nti][3] = bb1;
            }
        }

        #pragma unroll 8
        for (int kt = 0; kt < 32; kt++) {
            const int k0 = kt * 8;
            uint32_t a[2][4];
            const int abase = (k0 + fc) * SH + p0w + fg;
            #pragma unroll
            for (int mt = 0; mt < 2; mt++) {
                a[mt][0] = Hsu[abase + mt * 16];
                a[mt][1] = Hsu[abase + mt * 16 + 8];
                a[mt][2] = Hsu[abase + mt * 16 + 4 * SH];
                a[mt][3] = Hsu[abase + mt * 16 + 8 + 4 * SH];
            }
            #pragma unroll
            for (int nti = 0; nti < 3; nti++) {
                int nt = warpN + nti * 4;
                if (nt >= 9) break;
                uint32_t b[2];
                int baddr = (nt * 8 + fg) * SW2 + k0 + fc;
                b[0] = W2su[baddr];
                b[1] = W2su[baddr + 4];
                #pragma unroll
                for (int mt = 0; mt < 2; mt++)
                    mma_tf32(acc[mt][nti], a[mt], b);
            }
        }

        #pragma unroll
        for (int nti = 0; nti < 3; nti++) {
            int nt = warpN + nti * 4;
            if (nt >= 9) break;
            #pragma unroll
            for (int mt = 0; mt < 2; mt++) {
                #pragma unroll
                for (int i = 0; i < 4; i++) {
                    int pp = p0w + mt * 16 + fg + ((i >> 1) ? 8 : 0);
                    int oo = nt * 8 + 2 * fc + (i & 1);
                    Outs[oo * SO + pp] = acc[mt][nti][i];
                }
            }
        }
        __syncthreads();

        for (int idx = tid; idx < 64 * 72; idx += 256) {
            int pp = idx / 72;
            int oo = idx - pp * 72;
            int o  = o0 + oo;
            int Pg = P0 + pp;
            if (o < OUTCH && Pg < npts)
                out[Pg * OUTCH + o] = Outs[oo * SO + pp];
        }
        __syncthreads();
    }
}

// ---------------------------------------------------------------------------
extern "C" void kernel_launch(void* const* d_in, const int* in_sizes, int n_in,
                              void* d_out, int out_size) {
    const float* xyz    = (const float*)d_in[0];
    const float* planes = (const float*)d_in[1];
    const float* lines  = (const float*)d_in[2];
    const float* w1     = (const float*)d_in[3];
    const float* b1     = (const float*)d_in[4];
    const float* w2     = (const float*)d_in[5];
    const float* b2     = (const float*)d_in[6];
    float* out = (float*)d_out;

    int npts = in_sizes[0] / 3;

    cudaFuncSetAttribute(k_main, cudaFuncAttributeMaxDynamicSharedMemorySize, SMEM_BYTES);

    k_transpose_planes<<<3 * GRID_R * 5, 256>>>(planes);
    k_transpose_lines<<<(3 * GRID_R * NCOMP + 255) / 256, 256>>>(lines);

    int blocks = (npts + TP - 1) / TP;
    k_main<<<blocks, 256, SMEM_BYTES>>>(xyz, w1, b1, w2, b2, out, npts);
}

// round 4
// speedup vs baseline: 2.4199x; 1.3995x over previous
#include <cuda_runtime.h>
#include <cuda_bf16.h>
#include <math.h>
#include <stdint.h>

#define NCOMP 36
#define GRID_R 300
#define HID 256
#define INCH 129
#define OUTCH 129
#define CHUNK 2048
#define NBLK 148

// ---------------- global scratch ----------------
__device__ float g_planesT[3 * GRID_R * GRID_R * NCOMP];  // [pl][y][x][c]
__device__ float g_linesT[3 * GRID_R * NCOMP];            // [pl][z][c]
__device__ __nv_bfloat16 g_H[(size_t)CHUNK * 64 * 256];   // [lt][p][k] 64MB

// ---------------- transposes ----------------
__global__ void k_transpose_planes(const float* __restrict__ planes) {
    __shared__ float tile[NCOMP * 64];
    int chunk = blockIdx.x % 5;
    int y     = (blockIdx.x / 5) % GRID_R;
    int pl    = blockIdx.x / (5 * GRID_R);
    int x0 = chunk * 64;
    int w  = min(64, GRID_R - x0);
    for (int idx = threadIdx.x; idx < NCOMP * w; idx += blockDim.x) {
        int c = idx / w;
        int x = idx - c * w;
        tile[c * 64 + x] = planes[((pl * NCOMP + c) * GRID_R + y) * GRID_R + x0 + x];
    }
    __syncthreads();
    float* outp = g_planesT + ((pl * GRID_R + y) * GRID_R + x0) * NCOMP;
    for (int idx = threadIdx.x; idx < w * NCOMP; idx += blockDim.x) {
        int x = idx / NCOMP;
        int c = idx - x * NCOMP;
        outp[idx] = tile[c * 64 + x];
    }
}

__global__ void k_transpose_lines(const float* __restrict__ lines) {
    int idx = blockIdx.x * blockDim.x + threadIdx.x;
    const int total = 3 * GRID_R * NCOMP;
    if (idx < total) {
        int c  = idx % NCOMP;
        int z  = (idx / NCOMP) % GRID_R;
        int pl = idx / (NCOMP * GRID_R);
        g_linesT[idx] = lines[(pl * NCOMP + c) * GRID_R + z];
    }
}

// ---------------- helpers ----------------
__device__ __forceinline__ uint32_t f2tf(float x) {
    uint32_t u;
    asm("cvt.rna.tf32.f32 %0, %1;" : "=r"(u) : "f"(x));
    return u;
}
__device__ __forceinline__ void mma_tf32(float* d, const uint32_t* a, const uint32_t* b) {
    asm volatile(
        "mma.sync.aligned.m16n8k8.row.col.f32.tf32.tf32.f32 "
        "{%0,%1,%2,%3}, {%4,%5,%6,%7}, {%8,%9}, {%0,%1,%2,%3};"
        : "+f"(d[0]), "+f"(d[1]), "+f"(d[2]), "+f"(d[3])
        : "r"(a[0]), "r"(a[1]), "r"(a[2]), "r"(a[3]), "r"(b[0]), "r"(b[1]));
}
__device__ __forceinline__ void mma_bf16(float* d, const uint32_t* a, const uint32_t* b) {
    asm volatile(
        "mma.sync.aligned.m16n8k16.row.col.f32.bf16.bf16.f32 "
        "{%0,%1,%2,%3}, {%4,%5,%6,%7}, {%8,%9}, {%0,%1,%2,%3};"
        : "+f"(d[0]), "+f"(d[1]), "+f"(d[2]), "+f"(d[3])
        : "r"(a[0]), "r"(a[1]), "r"(a[2]), "r"(a[3]), "r"(b[0]), "r"(b[1]));
}
__device__ __forceinline__ void cpa16(uint32_t dst, const void* src) {
    asm volatile("cp.async.cg.shared.global [%0], [%1], 16;" :: "r"(dst), "l"(src));
}

// ===========================================================================
// Kernel A: persistent sample + embed + phase1 (tf32 MMA), w1 resident.
// smem: W1s tf32 [256][140] | Xs tf32 [136][72]
// ===========================================================================
#define SXA 72
#define SW1 140
#define A_NW1 (256 * SW1)                       // 35840
#define A_SMEM_WORDS (A_NW1 + 136 * SXA)        // 45632
#define A_SMEM_BYTES (A_SMEM_WORDS * 4)         // 182528

__global__ __launch_bounds__(256, 1) void k_phase1(
    const float* __restrict__ xyz,
    const float* __restrict__ w1, const float* __restrict__ b1,
    int tile0, int ntiles, int npts)
{
    extern __shared__ uint32_t smA[];
    uint32_t* W1s = smA;
    uint32_t* Xsu = smA + A_NW1;

    const int tid = threadIdx.x;

    // stage full w1 as tf32 (once per launch)
    for (int idx = tid; idx < A_NW1; idx += 256) {
        int j = idx / SW1, k = idx - j * SW1;
        float v = (k < INCH) ? w1[j * INCH + k] : 0.f;
        W1s[idx] = f2tf(v);
    }
    // zero X pad rows 129..135 (persist across tiles)
    for (int i = tid; i < 7 * SXA; i += 256)
        Xsu[129 * SXA + i] = 0u;
    __syncthreads();

    const int p = tid & 63;
    const int g = tid >> 6;
    const int warp = tid >> 5, lane = tid & 31;
    const int fg = lane >> 2, fc = lane & 3;
    const int warpM = warp >> 2, warpN = warp & 3;
    const int p0w = warpM * 32;

    for (int tile = tile0 + blockIdx.x; tile < tile0 + ntiles; tile += gridDim.x) {
        int P = tile * 64 + p;
        if (P >= npts) P = npts - 1;
        const float x = xyz[P * 3 + 0];
        const float y = xyz[P * 3 + 1];
        const float z = xyz[P * 3 + 2];

        // ---------- sampling / embedding into Xs [k][p] ----------
        if (g < 3) {
            float gx, gy, gl;
            if (g == 0)      { gx = x; gy = y; gl = z; }
            else if (g == 1) { gx = x; gy = z; gl = y; }
            else             { gx = y; gy = z; gl = x; }

            float fx = (gx + 1.f) * 0.5f * (float)(GRID_R - 1);
            float fy = (gy + 1.f) * 0.5f * (float)(GRID_R - 1);
            float fz = (gl + 1.f) * 0.5f * (float)(GRID_R - 1);
            int ix = min(max(__float2int_rd(fx), 0), GRID_R - 2);
            int iy = min(max(__float2int_rd(fy), 0), GRID_R - 2);
            int iz = min(max(__float2int_rd(fz), 0), GRID_R - 2);
            float tx = fx - (float)ix, ty = fy - (float)iy, tz = fz - (float)iz;

            float w00 = (1.f - tx) * (1.f - ty);
            float w01 = tx * (1.f - ty);
            float w10 = (1.f - tx) * ty;
            float w11 = tx * ty;
            float lz0 = 1.f - tz, lz1 = tz;

            const float* rowbase = g_planesT + ((g * GRID_R + iy) * GRID_R + ix) * NCOMP;
            const float4* b00 = (const float4*)(rowbase);
            const float4* b01 = (const float4*)(rowbase + NCOMP);
            const float4* b10 = (const float4*)(rowbase + GRID_R * NCOMP);
            const float4* b11 = (const float4*)(rowbase + GRID_R * NCOMP + NCOMP);
            const float4* l0p = (const float4*)(g_linesT + (g * GRID_R + iz) * NCOMP);
            const float4* l1p = (const float4*)(g_linesT + (g * GRID_R + iz + 1) * NCOMP);

            uint32_t* dst = Xsu + (21 + g * NCOMP) * SXA + p;
            #pragma unroll
            for (int c4 = 0; c4 < 9; c4++) {
                float4 a  = b00[c4];
                float4 b  = b01[c4];
                float4 cc = b10[c4];
                float4 d  = b11[c4];
                float4 l0 = l0p[c4];
                float4 l1 = l1p[c4];
                dst[(c4 * 4 + 0) * SXA] = f2tf((a.x * w00 + b.x * w01 + cc.x * w10 + d.x * w11) * (l0.x * lz0 + l1.x * lz1));
                dst[(c4 * 4 + 1) * SXA] = f2tf((a.y * w00 + b.y * w01 + cc.y * w10 + d.y * w11) * (l0.y * lz0 + l1.y * lz1));
                dst[(c4 * 4 + 2) * SXA] = f2tf((a.z * w00 + b.z * w01 + cc.z * w10 + d.z * w11) * (l0.z * lz0 + l1.z * lz1));
                dst[(c4 * 4 + 3) * SXA] = f2tf((a.w * w00 + b.w * w01 + cc.w * w10 + d.w * w11) * (l0.w * lz0 + l1.w * lz1));
            }
        } else {
            Xsu[0 * SXA + p] = f2tf(x);
            Xsu[1 * SXA + p] = f2tf(y);
            Xsu[2 * SXA + p] = f2tf(z);
            const float v[3] = {x, y, z};
            #pragma unroll
            for (int i = 0; i < 3; i++) {
                #pragma unroll
                for (int f = 0; f < 3; f++) {
                    float s, c;
                    sincosf(v[i] * (float)(1 << f), &s, &c);
                    Xsu[(3  + i * 3 + f) * SXA + p] = f2tf(s);
                    Xsu[(12 + i * 3 + f) * SXA + p] = f2tf(c);
                }
            }
        }
        __syncthreads();

        uint32_t* Hout = (uint32_t*)(g_H + (size_t)(tile - tile0) * 16384);

        // ---------- 2 passes of 128 hidden, MMA + softplus, direct STG ----------
        #pragma unroll 1
        for (int pass = 0; pass < 2; pass++) {
            const int j0 = pass * 128;
            const uint32_t* Wp = W1s + j0 * SW1;

            float acc[2][4][4];
            #pragma unroll
            for (int nt = 0; nt < 4; nt++) {
                int j = j0 + warpN * 32 + nt * 8 + 2 * fc;
                float bb0 = b1[j], bb1 = b1[j + 1];
                #pragma unroll
                for (int mt = 0; mt < 2; mt++) {
                    acc[mt][nt][0] = bb0; acc[mt][nt][1] = bb1;
                    acc[mt][nt][2] = bb0; acc[mt][nt][3] = bb1;
                }
            }

            #pragma unroll
            for (int kt = 0; kt < 17; kt++) {
                const int k0 = kt * 8;
                uint32_t a[2][4];
                const int abase = (k0 + fc) * SXA + p0w + fg;
                #pragma unroll
                for (int mt = 0; mt < 2; mt++) {
                    a[mt][0] = Xsu[abase + mt * 16];
                    a[mt][1] = Xsu[abase + mt * 16 + 8];
                    a[mt][2] = Xsu[abase + mt * 16 + 4 * SXA];
                    a[mt][3] = Xsu[abase + mt * 16 + 8 + 4 * SXA];
                }
                uint32_t b[4][2];
                #pragma unroll
                for (int nt = 0; nt < 4; nt++) {
                    int baddr = (warpN * 32 + nt * 8 + fg) * SW1 + k0 + fc;
                    b[nt][0] = Wp[baddr];
                    b[nt][1] = Wp[baddr + 4];
                }
                #pragma unroll
                for (int mt = 0; mt < 2; mt++)
                    #pragma unroll
                    for (int nt = 0; nt < 4; nt++)
                        mma_tf32(acc[mt][nt], a[mt], b[nt]);
            }

            // softplus + pack bf16x2 + direct global store (H[p][k] layout)
            #pragma unroll
            for (int mt = 0; mt < 2; mt++) {
                #pragma unroll
                for (int nt = 0; nt < 4; nt++) {
                    float sp[4];
                    #pragma unroll
                    for (int i = 0; i < 4; i++) {
                        float zz = 100.f * acc[mt][nt][i];
                        sp[i] = (fmaxf(zz, 0.f) + log1pf(expf(-fabsf(zz)))) * 0.01f;
                    }
                    int jj = j0 + warpN * 32 + nt * 8 + 2 * fc;
                    int pp = p0w + mt * 16 + fg;
                    __nv_bfloat162 h01 = __floats2bfloat162_rn(sp[0], sp[1]);
                    __nv_bfloat162 h23 = __floats2bfloat162_rn(sp[2], sp[3]);
                    Hout[(pp * 256 + jj) >> 1]       = *(uint32_t*)&h01;
                    Hout[((pp + 8) * 256 + jj) >> 1] = *(uint32_t*)&h23;
                }
            }
        }
        __syncthreads();  // Xs free for next tile
    }
}

// ===========================================================================
// Kernel B: persistent phase2 (bf16 MMA), w2 resident, cp.async H pipeline.
// smem bytes: W2s bf16 [144][264] | Hbuf[2] bf16 [64][264] | Outs f32 [64][148]
// ===========================================================================
#define SKH 264
#define B_W2_BYTES (144 * SKH * 2)                    // 76032
#define B_OFF_H    B_W2_BYTES
#define B_HBUF_BYTES (64 * SKH * 2)                   // 33792
#define B_OFF_OUT  (B_OFF_H + 2 * B_HBUF_BYTES)      // 143616
#define SOB 148
#define B_SMEM_BYTES (B_OFF_OUT + 64 * SOB * 4)      // 181504

__device__ __forceinline__ void prefetchH(char* smB, int bufsel, int lt, int tid) {
    const __nv_bfloat16* src = g_H + (size_t)lt * 16384;
    uint32_t dstbase = (uint32_t)__cvta_generic_to_shared(smB + B_OFF_H + bufsel * B_HBUF_BYTES);
    #pragma unroll
    for (int i = 0; i < 8; i++) {
        int c = tid + i * 256;
        int row = c >> 5, ch = c & 31;
        cpa16(dstbase + row * (SKH * 2) + ch * 16, src + row * 256 + ch * 8);
    }
    asm volatile("cp.async.commit_group;");
}

__global__ __launch_bounds__(256, 1) void k_phase2(
    const float* __restrict__ w2, const float* __restrict__ b2,
    float* __restrict__ out, int tile0, int ntiles, int npts)
{
    extern __shared__ char smB[];
    const int tid = threadIdx.x;
    const int warp = tid >> 5, lane = tid & 31;
    const int fg = lane >> 2, fc = lane & 3;
    const int warpM = warp >> 2, warpN = warp & 3;
    const int p0w = warpM * 32;

    // stage full w2 as bf16 [o][k], rows o>=129 zero
    for (int idx = tid; idx < 144 * 128; idx += 256) {
        int o = idx >> 7, k2 = idx & 127;
        float v0 = 0.f, v1 = 0.f;
        if (o < OUTCH) { v0 = w2[o * HID + 2 * k2]; v1 = w2[o * HID + 2 * k2 + 1]; }
        __nv_bfloat162 pr = __floats2bfloat162_rn(v0, v1);
        *(uint32_t*)(smB + o * (SKH * 2) + k2 * 4) = *(uint32_t*)&pr;
    }

    int t = tile0 + blockIdx.x;
    const int tend = tile0 + ntiles;
    if (t < tend) prefetchH(smB, 0, t - tile0, tid);
    __syncthreads();

    int buf = 0;
    for (; t < tend; t += gridDim.x) {
        int tn = t + gridDim.x;
        if (tn < tend) {
            prefetchH(smB, buf ^ 1, tn - tile0, tid);
            asm volatile("cp.async.wait_group 1;");
        } else {
            asm volatile("cp.async.wait_group 0;");
        }
        __syncthreads();

        const char* Hb = smB + B_OFF_H + buf * B_HBUF_BYTES;

        float acc[2][5][4];
        #pragma unroll
        for (int nti = 0; nti < 5; nti++) {
            int nt = warpN + nti * 4;
            if (nt >= 18) break;
            int o = nt * 8 + 2 * fc;
            float bb0 = (o < OUTCH) ? b2[o] : 0.f;
            float bb1 = (o + 1 < OUTCH) ? b2[o + 1] : 0.f;
            #pragma unroll
            for (int mt = 0; mt < 2; mt++) {
                acc[mt][nti][0] = bb0; acc[mt][nti][1] = bb1;
                acc[mt][nti][2] = bb0; acc[mt][nti][3] = bb1;
            }
        }

        #pragma unroll 4
        for (int kt = 0; kt < 16; kt++) {
            const int k0 = kt * 16;
            uint32_t a[2][4];
            #pragma unroll
            for (int mt = 0; mt < 2; mt++) {
                int pr = p0w + mt * 16 + fg;
                a[mt][0] = *(const uint32_t*)(Hb + pr * (SKH * 2) + (k0 + 2 * fc) * 2);
                a[mt][1] = *(const uint32_t*)(Hb + (pr + 8) * (SKH * 2) + (k0 + 2 * fc) * 2);
                a[mt][2] = *(const uint32_t*)(Hb + pr * (SKH * 2) + (k0 + 2 * fc + 8) * 2);
                a[mt][3] = *(const uint32_t*)(Hb + (pr + 8) * (SKH * 2) + (k0 + 2 * fc + 8) * 2);
            }
            #pragma unroll
            for (int nti = 0; nti < 5; nti++) {
                int nt = warpN + nti * 4;
                if (nt >= 18) break;
                uint32_t b[2];
                const char* wrow = smB + (nt * 8 + fg) * (SKH * 2);
                b[0] = *(const uint32_t*)(wrow + (k0 + 2 * fc) * 2);
                b[1] = *(const uint32_t*)(wrow + (k0 + 2 * fc + 8) * 2);
                mma_bf16(acc[0][nti], a[0], b);
                mma_bf16(acc[1][nti], a[1], b);
            }
        }

        float* Outs = (float*)(smB + B_OFF_OUT);
        #pragma unroll
        for (int nti = 0; nti < 5; nti++) {
            int nt = warpN + nti * 4;
            if (nt >= 18) break;
            #pragma unroll
            for (int mt = 0; mt < 2; mt++) {
                #pragma unroll
                for (int i = 0; i < 4; i++) {
                    int pp = p0w + mt * 16 + fg + ((i >> 1) ? 8 : 0);
                    int oo = nt * 8 + 2 * fc + (i & 1);
                    Outs[pp * SOB + oo] = acc[mt][nti][i];
                }
            }
        }
        __syncthreads();

        int rows = min(64, npts - t * 64);
        int total = rows * OUTCH;
        float* outp = out + (size_t)t * 64 * OUTCH;
        for (int idx = tid; idx < total; idx += 256) {
            int p = idx / OUTCH;
            int o = idx - p * OUTCH;
            outp[idx] = Outs[p * SOB + o];
        }
        __syncthreads();
        buf ^= 1;
    }
}

// ---------------------------------------------------------------------------
extern "C" void kernel_launch(void* const* d_in, const int* in_sizes, int n_in,
                              void* d_out, int out_size) {
    const float* xyz    = (const float*)d_in[0];
    const float* planes = (const float*)d_in[1];
    const float* lines  = (const float*)d_in[2];
    const float* w1     = (const float*)d_in[3];
    const float* b1     = (const float*)d_in[4];
    const float* w2     = (const float*)d_in[5];
    const float* b2     = (const float*)d_in[6];
    float* out = (float*)d_out;

    int npts = in_sizes[0] / 3;

    cudaFuncSetAttribute(k_phase1, cudaFuncAttributeMaxDynamicSharedMemorySize, A_SMEM_BYTES);
    cudaFuncSetAttribute(k_phase2, cudaFuncAttributeMaxDynamicSharedMemorySize, B_SMEM_BYTES);

    k_transpose_planes<<<3 * GRID_R * 5, 256>>>(planes);
    k_transpose_lines<<<(3 * GRID_R * NCOMP + 255) / 256, 256>>>(lines);

    int NT = (npts + 63) / 64;
    for (int t0 = 0; t0 < NT; t0 += CHUNK) {
        int nt = min(CHUNK, NT - t0);
        k_phase1<<<NBLK, 256, A_SMEM_BYTES>>>(xyz, w1, b1, t0, nt, npts);
        k_phase2<<<NBLK, 256, B_SMEM_BYTES>>>(w2, b2, out, t0, nt, npts);
    }
}